// round 1
// baseline (speedup 1.0000x reference)
#include <cuda_runtime.h>
#include <cuda_bf16.h>

// Problem constants
#define B     16
#define N1P   1024
#define N2P   4096
#define N1    (B * N1P)      // 16384 queries
#define N2    (B * N2P)      // 65536 sources
#define D_IN  64
#define H1    128
#define H2    256
#define KNB   32
#define NMAX  34             // 32 neighbors + self, padded to even
#define R2    0.04f

typedef unsigned long long ull;

// ---------------- scratch (static device globals; no allocations) ----------
__device__ float g_y2[(size_t)N2 * H1];   // x2 @ W1[:64] + b1   (33.5 MB)
__device__ int   g_nbr[(size_t)N1 * KNB];
__device__ int   g_cnt[N1];

// ---------------- f32x2 packed-math helpers --------------------------------
__device__ __forceinline__ ull pack2(float lo, float hi) {
    ull r; asm("mov.b64 %0, {%1,%2};" : "=l"(r) : "f"(lo), "f"(hi)); return r;
}
__device__ __forceinline__ void unpack2(ull v, float& lo, float& hi) {
    asm("mov.b64 {%0,%1}, %2;" : "=f"(lo), "=f"(hi) : "l"(v));
}
__device__ __forceinline__ ull fma2(ull a, ull b, ull c) {
    ull d; asm("fma.rn.f32x2 %0, %1, %2, %3;" : "=l"(d) : "l"(a), "l"(b), "l"(c)); return d;
}

// ================ kernel 1: y2 = x2 @ W1[0:64] + b1 ========================
__global__ __launch_bounds__(128) void precompute_y2_kernel(
    const float* __restrict__ x2, const float* __restrict__ W1,
    const float* __restrict__ b1)
{
    __shared__ float xr[D_IN];
    int r = blockIdx.x;
    int c = threadIdx.x;
    if (c < D_IN) xr[c] = x2[(size_t)r * D_IN + c];
    __syncthreads();
    float acc = b1[c];
    #pragma unroll
    for (int d = 0; d < D_IN; ++d)
        acc = fmaf(xr[d], W1[d * H1 + c], acc);
    g_y2[(size_t)r * H1 + c] = acc;
}

// ================ kernel 2: ball query (warp per query) ====================
// Sequential ascending scan + ballot prefix == "K lowest-index in-ball".
__global__ void ball_query_kernel(const float* __restrict__ pos1,
                                  const float* __restrict__ pos2)
{
    int gw   = (blockIdx.x * blockDim.x + threadIdx.x) >> 5;
    int lane = threadIdx.x & 31;
    if (gw >= N1) return;
    int q = gw;
    float qx = pos1[3 * q], qy = pos1[3 * q + 1], qz = pos1[3 * q + 2];
    float qn = qx * qx + qy * qy + qz * qz;
    int base = (q >> 10) << 12;     // (q / N1P) * N2P
    int cnt = 0;
    for (int chunk = 0; chunk < N2P / 32; ++chunk) {
        int s = base + chunk * 32 + lane;
        float sx = pos2[3 * s], sy = pos2[3 * s + 1], sz = pos2[3 * s + 2];
        // match reference's  |p1|^2 + |p2|^2 - 2 p1.p2  formulation
        float sn  = sx * sx + sy * sy + sz * sz;
        float dot = qx * sx + qy * sy + qz * sz;
        float sq  = qn + sn - 2.0f * dot;
        bool inb = (sq <= R2);
        unsigned m = __ballot_sync(0xffffffffu, inb);
        if (inb) {
            int slot = cnt + __popc(m & ((1u << lane) - 1u));
            if (slot < KNB) g_nbr[(size_t)q * KNB + slot] = s;
        }
        cnt += __popc(m);
        if (cnt >= KNB) break;     // uniform across warp
    }
    if (lane == 0) g_cnt[q] = (cnt < KNB) ? cnt : KNB;
}

// ================ kernel 3: per-query MLP + max aggregation ================
// Block of 128 threads handles one query. Thread c owns out channels c, c+128.
__global__ __launch_bounds__(128) void conv_kernel(
    const float* __restrict__ pos1, const float* __restrict__ pos2,
    const float* __restrict__ W1,   const float* __restrict__ W2,
    const float* __restrict__ b2,   float* __restrict__ out)
{
    __shared__ __align__(16) float m1s[H1 * NMAX];   // [k][n], row stride 34
    __shared__ int   jb[NMAX];
    __shared__ float dxs[NMAX], dys[NMAX], dzs[NMAX];

    int q = blockIdx.x;
    int c = threadIdx.x;
    int cnt   = g_cnt[q];
    int nrows = cnt + 1;                 // + self loop

    if (c < NMAX) {
        int j = (c < cnt) ? g_nbr[(size_t)q * KNB + c] : q;  // self / pad -> q
        jb[c] = j;
        float px = pos1[3 * q], py = pos1[3 * q + 1], pz = pos1[3 * q + 2];
        dxs[c] = pos2[3 * j]     - px;
        dys[c] = pos2[3 * j + 1] - py;
        dzs[c] = pos2[3 * j + 2] - pz;
    }
    __syncthreads();

    // ---- pass 1: m1[n][c] = relu(y2[j_n][c] + dpos_n . W1[64:67, c]) ----
    float wx = W1[64 * H1 + c], wy = W1[65 * H1 + c], wz = W1[66 * H1 + c];
    float* mrow = m1s + c * NMAX;
    #pragma unroll
    for (int n = 0; n < NMAX; ++n) {
        float v = 0.0f;                                  // pad rows -> 0
        if (n < nrows) {
            float t = g_y2[(size_t)jb[n] * H1 + c];
            t = fmaf(dxs[n], wx, t);
            t = fmaf(dys[n], wy, t);
            t = fmaf(dzs[n], wz, t);
            v = fmaxf(t, 0.0f);
        }
        mrow[n] = v;
    }
    __syncthreads();

    // ---- pass 2: acc[n] = b2 + sum_k m1[n][k] * W2[k][c2], f32x2 pairs ----
    ull accA[NMAX / 2], accB[NMAX / 2];
    {
        float ba = b2[c], bb = b2[c + 128];
        ull ia = pack2(ba, ba), ib = pack2(bb, bb);
        #pragma unroll
        for (int p = 0; p < NMAX / 2; ++p) { accA[p] = ia; accB[p] = ib; }
    }
    #pragma unroll 2
    for (int k = 0; k < H1; ++k) {
        float w0 = W2[k * H2 + c];
        float w1 = W2[k * H2 + 128 + c];
        ull wp0 = pack2(w0, w0);
        ull wp1 = pack2(w1, w1);
        const ull* mr = (const ull*)(m1s + k * NMAX);   // broadcast loads
        #pragma unroll
        for (int p = 0; p < NMAX / 2; ++p) {
            ull m = mr[p];
            accA[p] = fma2(m, wp0, accA[p]);
            accB[p] = fma2(m, wp1, accB[p]);
        }
    }

    // ---- relu + max over valid rows ----
    float mxA = -3.0e38f, mxB = -3.0e38f;
    #pragma unroll
    for (int p = 0; p < NMAX / 2; ++p) {
        float a0, a1, bb0, bb1;
        unpack2(accA[p], a0, a1);
        unpack2(accB[p], bb0, bb1);
        if (2 * p < nrows) {
            mxA = fmaxf(mxA, fmaxf(a0, 0.0f));
            mxB = fmaxf(mxB, fmaxf(bb0, 0.0f));
        }
        if (2 * p + 1 < nrows) {
            mxA = fmaxf(mxA, fmaxf(a1, 0.0f));
            mxB = fmaxf(mxB, fmaxf(bb1, 0.0f));
        }
    }
    out[(size_t)q * H2 + c]       = mxA;
    out[(size_t)q * H2 + 128 + c] = mxB;
}

// =========================== launcher ======================================
extern "C" void kernel_launch(void* const* d_in, const int* in_sizes, int n_in,
                              void* d_out, int out_size)
{
    // inputs: 0:x1 1:pos1 2:batch1(i64) 3:x2 4:pos2 5:batch2(i64)
    //         6:W1[67,128] 7:b1[128] 8:W2[128,256] 9:b2[256]
    const float* pos1 = (const float*)d_in[1];
    const float* x2   = (const float*)d_in[3];
    const float* pos2 = (const float*)d_in[4];
    const float* W1   = (const float*)d_in[6];
    const float* b1   = (const float*)d_in[7];
    const float* W2   = (const float*)d_in[8];
    const float* b2   = (const float*)d_in[9];
    float* out = (float*)d_out;

    precompute_y2_kernel<<<N2, 128>>>(x2, W1, b1);
    ball_query_kernel<<<(N1 * 32 + 255) / 256, 256>>>(pos1, pos2);
    conv_kernel<<<N1, 128>>>(pos1, pos2, W1, W2, b2, out);
}

// round 4
// speedup vs baseline: 1.2139x; 1.2139x over previous
#include <cuda_runtime.h>
#include <cuda_bf16.h>

// Problem constants
#define B     16
#define N1P   1024
#define N2P   4096
#define N1    (B * N1P)      // 16384 queries
#define N2    (B * N2P)      // 65536 sources
#define D_IN  64
#define H1    128
#define H2    256
#define KNB   32
#define NMAX  34             // 32 neighbors + self
#define NST   36             // smem row stride (floats), 144B = 16B aligned
#define R2    0.04f

typedef unsigned long long ull;

// ---------------- scratch (static device globals; no allocations) ----------
__device__ float g_y2[(size_t)N2 * H1];   // x2 @ W1[:64] + b1   (33.5 MB)
__device__ int   g_nbr[(size_t)N1 * KNB];
__device__ int   g_cnt[N1];

// ---------------- f32x2 packed-math helpers --------------------------------
__device__ __forceinline__ ull pack2(float lo, float hi) {
    ull r; asm("mov.b64 %0, {%1,%2};" : "=l"(r) : "f"(lo), "f"(hi)); return r;
}
__device__ __forceinline__ void unpack2(ull v, float& lo, float& hi) {
    asm("mov.b64 {%0,%1}, %2;" : "=f"(lo), "=f"(hi) : "l"(v));
}
__device__ __forceinline__ ull fma2(ull a, ull b, ull c) {
    ull d; asm("fma.rn.f32x2 %0, %1, %2, %3;" : "=l"(d) : "l"(a), "l"(b), "l"(c)); return d;
}

// ================ kernel 1: y2 = x2 @ W1[0:64] + b1 ========================
// Block = 128 threads (thread c owns output column c, W1[:,c] in registers).
// Block processes 64 rows; x rows staged once in smem, read via LDS.128.
#define PR_ROWS 64
__global__ __launch_bounds__(128) void precompute_y2_kernel(
    const float* __restrict__ x2, const float* __restrict__ W1,
    const float* __restrict__ b1)
{
    __shared__ __align__(16) float xs[PR_ROWS * D_IN];   // 16 KB
    int c = threadIdx.x;

    float w[D_IN];
    #pragma unroll
    for (int d = 0; d < D_IN; ++d) w[d] = W1[d * H1 + c];
    float bc = b1[c];

    size_t rbase = (size_t)blockIdx.x * PR_ROWS;
    const float4* src  = (const float4*)(x2 + rbase * D_IN);
    float4*       dst4 = (float4*)xs;
    for (int i = c; i < PR_ROWS * D_IN / 4; i += 128) dst4[i] = src[i];
    __syncthreads();

    for (int r = 0; r < PR_ROWS; ++r) {
        const float4* xr = (const float4*)(xs + r * D_IN);
        float a = bc;
        #pragma unroll
        for (int t = 0; t < D_IN / 4; ++t) {
            float4 xv = xr[t];
            a = fmaf(xv.x, w[4 * t],     a);
            a = fmaf(xv.y, w[4 * t + 1], a);
            a = fmaf(xv.z, w[4 * t + 2], a);
            a = fmaf(xv.w, w[4 * t + 3], a);
        }
        g_y2[(rbase + r) * H1 + c] = a;
    }
}

// ================ kernel 2: ball query (warp per query) ====================
// Sequential ascending scan + ballot prefix == "K lowest-index in-ball".
__global__ void ball_query_kernel(const float* __restrict__ pos1,
                                  const float* __restrict__ pos2)
{
    int gw   = (blockIdx.x * blockDim.x + threadIdx.x) >> 5;
    int lane = threadIdx.x & 31;
    if (gw >= N1) return;
    int q = gw;
    float qx = pos1[3 * q], qy = pos1[3 * q + 1], qz = pos1[3 * q + 2];
    float qn = qx * qx + qy * qy + qz * qz;
    int base = (q >> 10) << 12;     // (q / N1P) * N2P
    int cnt = 0;
    for (int chunk = 0; chunk < N2P / 32; ++chunk) {
        int s = base + chunk * 32 + lane;
        float sx = pos2[3 * s], sy = pos2[3 * s + 1], sz = pos2[3 * s + 2];
        // match reference's  |p1|^2 + |p2|^2 - 2 p1.p2  formulation
        float sn  = sx * sx + sy * sy + sz * sz;
        float dot = qx * sx + qy * sy + qz * sz;
        float sq  = qn + sn - 2.0f * dot;
        bool inb = (sq <= R2);
        unsigned m = __ballot_sync(0xffffffffu, inb);
        if (inb) {
            int slot = cnt + __popc(m & ((1u << lane) - 1u));
            if (slot < KNB) g_nbr[(size_t)q * KNB + slot] = s;
        }
        cnt += __popc(m);
        if (cnt >= KNB) break;     // uniform across warp
    }
    if (lane == 0) g_cnt[q] = (cnt < KNB) ? cnt : KNB;
}

// ================ kernel 3: per-query MLP + max aggregation ================
// Block of 128 threads handles one query. Thread c owns out channels c, c+128.
__global__ __launch_bounds__(128, 4) void conv_kernel(
    const float* __restrict__ pos1, const float* __restrict__ pos2,
    const float* __restrict__ W1,   const float* __restrict__ W2,
    const float* __restrict__ b2,   float* __restrict__ out)
{
    __shared__ __align__(16) float m1s[H1 * NST];   // [k][n], row stride 36
    __shared__ int   jb[NMAX];
    __shared__ float dxs[NMAX], dys[NMAX], dzs[NMAX];

    int q = blockIdx.x;
    int c = threadIdx.x;
    int cnt   = g_cnt[q];
    int nrows = cnt + 1;                 // + self loop

    if (c < NMAX) {
        int j = (c < cnt) ? g_nbr[(size_t)q * KNB + c] : q;  // self / pad -> q
        jb[c] = j;
        float px = pos1[3 * q], py = pos1[3 * q + 1], pz = pos1[3 * q + 2];
        dxs[c] = pos2[3 * j]     - px;
        dys[c] = pos2[3 * j + 1] - py;
        dzs[c] = pos2[3 * j + 2] - pz;
    }
    __syncthreads();

    // ---- pass 1: m1[n][c] = relu(y2[j_n][c] + dpos_n . W1[64:67, c]) ----
    float wx = W1[64 * H1 + c], wy = W1[65 * H1 + c], wz = W1[66 * H1 + c];
    float* mrow = m1s + c * NST;
    #pragma unroll
    for (int n = 0; n < NMAX; ++n) {
        float v = 0.0f;                                  // pad rows -> 0
        if (n < nrows) {
            float t = g_y2[(size_t)jb[n] * H1 + c];
            t = fmaf(dxs[n], wx, t);
            t = fmaf(dys[n], wy, t);
            t = fmaf(dzs[n], wz, t);
            v = fmaxf(t, 0.0f);
        }
        mrow[n] = v;
    }
    __syncthreads();

    // ---- pass 2: acc[n] = b2 + sum_k m1[n][k] * W2[k][c2], f32x2 pairs ----
    ull accA[NMAX / 2], accB[NMAX / 2];
    {
        float ba = b2[c], bb = b2[c + 128];
        ull ia = pack2(ba, ba), ib = pack2(bb, bb);
        #pragma unroll
        for (int p = 0; p < NMAX / 2; ++p) { accA[p] = ia; accB[p] = ib; }
    }

    float w0 = W2[c];          // prefetched weight pair for k=0
    float w1 = W2[128 + c];
    #pragma unroll 2
    for (int k = 0; k < H1; ++k) {
        ull wp0 = pack2(w0, w0);
        ull wp1 = pack2(w1, w1);
        if (k + 1 < H1) {                       // prefetch next k's weights
            w0 = W2[(k + 1) * H2 + c];
            w1 = W2[(k + 1) * H2 + 128 + c];
        }
        const ulonglong2* mr2 = (const ulonglong2*)(m1s + k * NST);  // 16B aligned
        #pragma unroll
        for (int p = 0; p < 8; ++p) {           // pairs 0..15 via LDS.128
            ulonglong2 mm = mr2[p];
            accA[2 * p]     = fma2(mm.x, wp0, accA[2 * p]);
            accA[2 * p + 1] = fma2(mm.y, wp0, accA[2 * p + 1]);
            accB[2 * p]     = fma2(mm.x, wp1, accB[2 * p]);
            accB[2 * p + 1] = fma2(mm.y, wp1, accB[2 * p + 1]);
        }
        {                                       // pair 16 (rows 32,33) via LDS.64
            ull mm = ((const ull*)(m1s + k * NST))[16];
            accA[16] = fma2(mm, wp0, accA[16]);
            accB[16] = fma2(mm, wp1, accB[16]);
        }
    }

    // ---- relu + max over valid rows ----
    float mxA = -3.0e38f, mxB = -3.0e38f;
    #pragma unroll
    for (int p = 0; p < NMAX / 2; ++p) {
        float a0, a1, bb0, bb1;
        unpack2(accA[p], a0, a1);
        unpack2(accB[p], bb0, bb1);
        if (2 * p < nrows) {
            mxA = fmaxf(mxA, fmaxf(a0, 0.0f));
            mxB = fmaxf(mxB, fmaxf(bb0, 0.0f));
        }
        if (2 * p + 1 < nrows) {
            mxA = fmaxf(mxA, fmaxf(a1, 0.0f));
            mxB = fmaxf(mxB, fmaxf(bb1, 0.0f));
        }
    }
    out[(size_t)q * H2 + c]       = mxA;
    out[(size_t)q * H2 + 128 + c] = mxB;
}

// =========================== launcher ======================================
extern "C" void kernel_launch(void* const* d_in, const int* in_sizes, int n_in,
                              void* d_out, int out_size)
{
    // inputs: 0:x1 1:pos1 2:batch1(i64) 3:x2 4:pos2 5:batch2(i64)
    //         6:W1[67,128] 7:b1[128] 8:W2[128,256] 9:b2[256]
    const float* pos1 = (const float*)d_in[1];
    const float* x2   = (const float*)d_in[3];
    const float* pos2 = (const float*)d_in[4];
    const float* W1   = (const float*)d_in[6];
    const float* b1   = (const float*)d_in[7];
    const float* W2   = (const float*)d_in[8];
    const float* b2   = (const float*)d_in[9];
    float* out = (float*)d_out;

    precompute_y2_kernel<<<N2 / PR_ROWS, 128>>>(x2, W1, b1);
    ball_query_kernel<<<(N1 * 32 + 255) / 256, 256>>>(pos1, pos2);
    conv_kernel<<<N1, 128>>>(pos1, pos2, W1, W2, b2, out);
}